// round 6
// baseline (speedup 1.0000x reference)
#include <cuda_runtime.h>

// EdgeAugmentation, single-launch, last-finisher election (v3: no grid barrier).
// LayerNorm over a singleton axis => every score == beta => stable top_k picks
// the first TOPK row-major (i,j) per graph that are neither an existing
// same-graph edge nor diagonal. Output buffer is float32.
//
// 64 blocks. Phase 1: block b copies its 1/64 slice of edge_index to the
// output and ORs edge bits into the global per-graph bitmap (relaxed REDs).
// Election: each block's t0 does atom.acq_rel.gpu.add on a monotone ticket;
// the block drawing (ticket % 64) == 63 synchronizes-with all 63 prior
// releases and therefore sees every RED. It alone computes top-16 for all 64
// graphs and zeroes the bitmap (restoring the precondition for the next graph
// replay; device globals are zero-init at load, so call #1 is clean too).
// The other 63 blocks exit immediately -- no spinning, no broadcast.

#define E_EDGES 65536
#define BQ      64
#define TOPK_K  16
#define AUG     (E_EDGES + BQ * TOPK_K)   // 66560 columns in aug_edge_index
#define WORDS   512                        // 128*128 bits / 32

__device__ unsigned g_exist[BQ][WORDS];    // zero-init; restored to zero each run
__device__ unsigned g_bar;                 // monotone ticket counter

__device__ __forceinline__ unsigned atom_add_acqrel_gpu(unsigned* p, unsigned v) {
    unsigned old;
    asm volatile("atom.acq_rel.gpu.global.add.u32 %0, [%1], %2;"
                 : "=r"(old) : "l"(p), "r"(v) : "memory");
    return old;
}

__global__ void __launch_bounds__(512, 1)
fused_kernel(const int* __restrict__ ei, float* __restrict__ out, int write_count) {
    const int b = blockIdx.x;
    const int t = threadIdx.x;      // 0..511

    // ---- Phase 1: copy own slice + set existence bits (2 edges/thread) ----
    {
        int e2 = (b << 9) + t;                      // int2 index: b*512 + t
        int2 s2 = ((const int2*)ei)[e2];
        int2 d2 = ((const int2*)(ei + E_EDGES))[e2];
        ((float2*)out)[e2]         = make_float2((float)s2.x, (float)s2.y);
        ((float2*)(out + AUG))[e2] = make_float2((float)d2.x, (float)d2.y);

        int g0 = s2.x >> 7;
        if ((d2.x >> 7) == g0) {
            unsigned bit = ((unsigned)(s2.x & 127) << 7) | (unsigned)(d2.x & 127);
            atomicOr(&g_exist[g0][bit >> 5], 1u << (bit & 31));   // RED (no return)
        }
        int g1 = s2.y >> 7;
        if ((d2.y >> 7) == g1) {
            unsigned bit = ((unsigned)(s2.y & 127) << 7) | (unsigned)(d2.y & 127);
            atomicOr(&g_exist[g1][bit >> 5], 1u << (bit & 31));
        }
    }

    // ---- Election: last finisher inherits phase 3 ----
    __syncthreads();                                  // all block REDs issued
    __shared__ int elected;
    if (t == 0) {
        unsigned ticket = atom_add_acqrel_gpu(&g_bar, 1u);
        elected = ((ticket & (BQ - 1u)) == (BQ - 1u)) ? 1 : 0;
    }
    __syncthreads();                                  // publish visibility to block
    if (!elected) return;

    // ---- Phase 3 (elected block only): top-16 for ALL 64 graphs ----
    const int lane = t & 31;
    const int w    = t >> 5;                          // warp 0..15

    #pragma unroll
    for (int gi = 0; gi < BQ / 16; gi++) {            // 4 graphs per warp
        const int g    = w * 4 + gi;
        const int boff = g << 7;

        // Each lane owns words [16*lane, 16*lane+16) of graph g's bitmap.
        const uint4* src = (const uint4*)(&g_exist[g][lane << 4]);
        uint4 q0 = __ldcg(src + 0);
        uint4 q1 = __ldcg(src + 1);
        uint4 q2 = __ldcg(src + 2);
        uint4 q3 = __ldcg(src + 3);

        unsigned words[16] = { q0.x, q0.y, q0.z, q0.w,  q1.x, q1.y, q1.z, q1.w,
                               q2.x, q2.y, q2.z, q2.w,  q3.x, q3.y, q3.z, q3.w };
        unsigned m[16];
        int c = 0;
        #pragma unroll
        for (int j = 0; j < 16; j++) {
            int lo = ((lane << 4) + j) << 5;
            unsigned mm = ~words[j];
            int p = ((lo + 128) / 129) * 129;         // diagonal bit 129*i in range?
            if (p < lo + 32) mm &= ~(1u << (p - lo));
            m[j] = mm;
            c += __popc(mm);
        }

        // Inclusive warp scan of popcounts -> exclusive rank per lane.
        int v = c;
        #pragma unroll
        for (int off = 1; off < 32; off <<= 1) {
            int x = __shfl_up_sync(0xffffffffu, v, off);
            if (lane >= off) v += x;
        }
        int r = v - c;                                // exclusive rank

        if (r < TOPK_K && c) {
            #pragma unroll
            for (int j = 0; j < 16 && r < TOPK_K; j++) {
                unsigned mm = m[j];
                int lo = ((lane << 4) + j) << 5;
                while (mm && r < TOPK_K) {
                    int bi = __ffs(mm) - 1;
                    mm &= mm - 1;
                    int bitpos = lo + bi;
                    out[E_EDGES + g * TOPK_K + r]       = (float)(boff + (bitpos >> 7));
                    out[AUG + E_EDGES + g * TOPK_K + r] = (float)(boff + (bitpos & 127));
                    r++;
                }
            }
        }

        // Restore all-zero bitmap for the next replay.
        uint4 z = make_uint4(0u, 0u, 0u, 0u);
        uint4* dst = (uint4*)(&g_exist[g][lane << 4]);
        dst[0] = z; dst[1] = z; dst[2] = z; dst[3] = z;
    }

    if (t == 0 && write_count) out[2 * AUG] = (float)(BQ * TOPK_K);  // added_count
}

extern "C" void kernel_launch(void* const* d_in, const int* in_sizes, int n_in,
                              void* d_out, int out_size) {
    // Locate edge_index by its unique element count (2 * E = 131072, int32).
    const int* ei = nullptr;
    for (int i = 0; i < n_in; i++) {
        if (in_sizes[i] == 2 * E_EDGES) { ei = (const int*)d_in[i]; break; }
    }
    float* out = (float*)d_out;

    fused_kernel<<<BQ, 512>>>(ei, out, (out_size > 2 * AUG) ? 1 : 0);
}

// round 7
// speedup vs baseline: 1.9143x; 1.9143x over previous
#include <cuda_runtime.h>

// EdgeAugmentation, single-launch persistent formulation (v4 = R5 structure,
// slimmed). LayerNorm over a singleton axis => every score == beta => stable
// top_k picks the first TOPK row-major (i,j) per graph that are neither an
// existing same-graph edge nor diagonal. Output buffer is float32.
//
// 64 blocks x 256 threads.
// Phase 1: block b copies its 1/64 slice of edge_index (one int4 packet per
//          thread) to the output and ORs edge bits into the global per-graph
//          bitmap (relaxed REDs).
// Phase 2: grid barrier via atom.release.gpu ticket + ld.acquire.gpu spin
//          (monotone counter -- replay-safe, no reset, no L1 flush).
// Phase 3: block b rank-scans graph b's free bitmap (2 words/thread) for the
//          first 16 cells, then zeroes its slice, restoring the all-zero
//          precondition for the next graph replay (device globals are
//          zero-initialized at load, so call #1 is clean too).

#define E_EDGES 65536
#define BQ      64
#define TOPK_K  16
#define AUG     (E_EDGES + BQ * TOPK_K)   // 66560 columns in aug_edge_index
#define WORDS   512                        // 128*128 bits / 32

__device__ unsigned g_exist[BQ][WORDS];    // zero-init; restored to zero each run
__device__ unsigned g_bar;                 // monotone ticket counter

__device__ __forceinline__ unsigned atom_add_release_gpu(unsigned* p, unsigned v) {
    unsigned old;
    asm volatile("atom.release.gpu.global.add.u32 %0, [%1], %2;"
                 : "=r"(old) : "l"(p), "r"(v) : "memory");
    return old;
}
__device__ __forceinline__ unsigned ld_acquire_gpu(const unsigned* p) {
    unsigned v;
    asm volatile("ld.acquire.gpu.global.u32 %0, [%1];"
                 : "=r"(v) : "l"(p) : "memory");
    return v;
}

__global__ void __launch_bounds__(256, 1)
fused_kernel(const int* __restrict__ ei, float* __restrict__ out, int write_count) {
    const int b = blockIdx.x;
    const int t = threadIdx.x;      // 0..255

    // ---- Phase 1: copy own slice + set existence bits (4 edges/thread) ----
    {
        int p4 = (b << 8) + t;                      // int4 packet index
        int4 s4 = ((const int4*)ei)[p4];
        int4 d4 = ((const int4*)(ei + E_EDGES))[p4];
        ((float4*)out)[p4] =
            make_float4((float)s4.x, (float)s4.y, (float)s4.z, (float)s4.w);
        ((float4*)(out + AUG))[p4] =
            make_float4((float)d4.x, (float)d4.y, (float)d4.z, (float)d4.w);

        int ss[4] = { s4.x, s4.y, s4.z, s4.w };
        int dd[4] = { d4.x, d4.y, d4.z, d4.w };
        #pragma unroll
        for (int k = 0; k < 4; k++) {
            int g = ss[k] >> 7;
            if ((dd[k] >> 7) == g) {
                unsigned bit = ((unsigned)(ss[k] & 127) << 7) | (unsigned)(dd[k] & 127);
                atomicOr(&g_exist[g][bit >> 5], 1u << (bit & 31));   // RED
            }
        }
        if (b == 0 && t == 0 && write_count)
            out[2 * AUG] = (float)(BQ * TOPK_K);    // added_count, off the tail
    }

    // ---- Phase 2: grid barrier, release/acquire (no L1 flush) ----
    __syncthreads();                                  // all block REDs issued
    if (t == 0) {
        unsigned ticket = atom_add_release_gpu(&g_bar, 1u);
        unsigned target = ((ticket >> 6) + 1u) << 6;  // end of this group of 64
        while (ld_acquire_gpu(&g_bar) < target) { }
    }
    __syncthreads();

    // ---- Phase 3: rank-scan graph b's free bitmap; emit first TOPK cells ----
    const int lane = t & 31;
    const int wid  = t >> 5;                          // warp 0..7
    const int boff = b << 7;

    uint2 q = __ldcg((const uint2*)&g_exist[b][t << 1]);   // 2 words/thread
    *((uint2*)&g_exist[b][t << 1]) = make_uint2(0u, 0u);   // restore precondition

    unsigned m0 = ~q.x, m1 = ~q.y;
    // Clear the (at most one) diagonal bit per word: positions p = 129*i.
    int lo0 = t << 6;                                 // bit base of word 2t
    int lo1 = lo0 + 32;
    int p0 = ((lo0 + 128) / 129) * 129;
    int p1 = ((lo1 + 128) / 129) * 129;
    if (p0 < lo0 + 32) m0 &= ~(1u << (p0 - lo0));
    if (p1 < lo1 + 32) m1 &= ~(1u << (p1 - lo1));

    int c = __popc(m0) + __popc(m1);

    // Inclusive warp scan of popcounts.
    int v = c;
    #pragma unroll
    for (int off = 1; off < 32; off <<= 1) {
        int x = __shfl_up_sync(0xffffffffu, v, off);
        if (lane >= off) v += x;
    }
    __shared__ int wsum[8];
    if (lane == 31) wsum[wid] = v;
    __syncthreads();
    if (wid == 0) {
        int x = (lane < 8) ? wsum[lane] : 0;
        #pragma unroll
        for (int off = 1; off < 8; off <<= 1) {
            int y = __shfl_up_sync(0xffffffffu, x, off);
            if (lane >= off) x += y;
        }
        if (lane < 8) wsum[lane] = x;
    }
    __syncthreads();

    int r = v - c + (wid > 0 ? wsum[wid - 1] : 0);    // exclusive rank over block

    if (r < TOPK_K) {
        unsigned mm = m0;
        int lo = lo0;
        #pragma unroll
        for (int half = 0; half < 2; half++) {
            while (mm && r < TOPK_K) {
                int bi = __ffs(mm) - 1;
                mm &= mm - 1;
                int bitpos = lo + bi;
                out[E_EDGES + b * TOPK_K + r]       = (float)(boff + (bitpos >> 7));
                out[AUG + E_EDGES + b * TOPK_K + r] = (float)(boff + (bitpos & 127));
                r++;
            }
            mm = m1; lo = lo1;
        }
    }
}

extern "C" void kernel_launch(void* const* d_in, const int* in_sizes, int n_in,
                              void* d_out, int out_size) {
    // Locate edge_index by its unique element count (2 * E = 131072, int32).
    const int* ei = nullptr;
    for (int i = 0; i < n_in; i++) {
        if (in_sizes[i] == 2 * E_EDGES) { ei = (const int*)d_in[i]; break; }
    }
    float* out = (float*)d_out;

    fused_kernel<<<BQ, 256>>>(ei, out, (out_size > 2 * AUG) ? 1 : 0);
}

// round 8
// speedup vs baseline: 1.9706x; 1.0294x over previous
#include <cuda_runtime.h>

// EdgeAugmentation, single-launch persistent formulation (v5: 32 blocks,
// 2 graphs/block, backoff barrier). LayerNorm over a singleton axis => every
// score == beta => stable top_k picks the first TOPK row-major (i,j) per graph
// that are neither an existing same-graph edge nor diagonal. Output = float32.
//
// 32 blocks x 512 threads.
// Phase 1: block b copies its 1/32 slice of edge_index (one int4 packet per
//          thread) to the output and ORs edge bits into the global per-graph
//          bitmap (relaxed REDs).
// Phase 2: grid barrier via atom.release.gpu ticket + ld.acquire.gpu spin with
//          __nanosleep backoff (monotone counter -- replay-safe, no L1 flush).
// Phase 3: warps 0-7 scan graph 2b, warps 8-15 scan graph 2b+1 (2 words per
//          thread), emit the first 16 free cells, then zero the slice --
//          restoring the all-zero precondition for the next graph replay
//          (device globals are zero-init at load, so call #1 is clean too).

#define E_EDGES 65536
#define BQ      64
#define TOPK_K  16
#define AUG     (E_EDGES + BQ * TOPK_K)   // 66560 columns in aug_edge_index
#define WORDS   512                        // 128*128 bits / 32
#define NBLK    32

__device__ unsigned g_exist[BQ][WORDS];    // zero-init; restored to zero each run
__device__ unsigned g_bar;                 // monotone ticket counter

__device__ __forceinline__ unsigned atom_add_release_gpu(unsigned* p, unsigned v) {
    unsigned old;
    asm volatile("atom.release.gpu.global.add.u32 %0, [%1], %2;"
                 : "=r"(old) : "l"(p), "r"(v) : "memory");
    return old;
}
__device__ __forceinline__ unsigned ld_acquire_gpu(const unsigned* p) {
    unsigned v;
    asm volatile("ld.acquire.gpu.global.u32 %0, [%1];"
                 : "=r"(v) : "l"(p) : "memory");
    return v;
}

__global__ void __launch_bounds__(512, 1)
fused_kernel(const int* __restrict__ ei, float* __restrict__ out, int write_count) {
    const int b = blockIdx.x;
    const int t = threadIdx.x;      // 0..511

    // ---- Phase 1: copy own slice + set existence bits (4 edges/thread) ----
    {
        int p4 = (b << 9) + t;                      // int4 packet index
        int4 s4 = ((const int4*)ei)[p4];
        int4 d4 = ((const int4*)(ei + E_EDGES))[p4];
        ((float4*)out)[p4] =
            make_float4((float)s4.x, (float)s4.y, (float)s4.z, (float)s4.w);
        ((float4*)(out + AUG))[p4] =
            make_float4((float)d4.x, (float)d4.y, (float)d4.z, (float)d4.w);

        int ss[4] = { s4.x, s4.y, s4.z, s4.w };
        int dd[4] = { d4.x, d4.y, d4.z, d4.w };
        #pragma unroll
        for (int k = 0; k < 4; k++) {
            int g = ss[k] >> 7;
            if ((dd[k] >> 7) == g) {
                unsigned bit = ((unsigned)(ss[k] & 127) << 7) | (unsigned)(dd[k] & 127);
                atomicOr(&g_exist[g][bit >> 5], 1u << (bit & 31));   // RED
            }
        }
        if (b == 0 && t == 0 && write_count)
            out[2 * AUG] = (float)(BQ * TOPK_K);    // added_count, off the tail
    }

    // ---- Phase 2: grid barrier, release/acquire with backoff ----
    __syncthreads();                                  // all block REDs issued
    if (t == 0) {
        unsigned ticket = atom_add_release_gpu(&g_bar, 1u);
        unsigned target = ((ticket >> 5) + 1u) << 5;  // end of this group of 32
        if (ld_acquire_gpu(&g_bar) < target) {
            do { __nanosleep(32); } while (ld_acquire_gpu(&g_bar) < target);
        }
    }
    __syncthreads();

    // ---- Phase 3: rank-scan two graphs' free bitmaps (one per 8 warps) ----
    const int lane = t & 31;
    const int half = t >> 8;                          // 0 or 1
    const int u    = t & 255;                         // thread within half
    const int hw   = (t >> 5) & 7;                    // warp within half, 0..7
    const int g    = (b << 1) | half;
    const int boff = g << 7;

    uint2 q = __ldcg((const uint2*)&g_exist[g][u << 1]);   // 2 words/thread
    *((uint2*)&g_exist[g][u << 1]) = make_uint2(0u, 0u);   // restore precondition

    unsigned m0 = ~q.x, m1 = ~q.y;
    // Clear the (at most one) diagonal bit per word: positions p = 129*i.
    int lo0 = u << 6;                                 // bit base of word 2u
    int lo1 = lo0 + 32;
    int p0 = ((lo0 + 128) / 129) * 129;
    int p1 = ((lo1 + 128) / 129) * 129;
    if (p0 < lo0 + 32) m0 &= ~(1u << (p0 - lo0));
    if (p1 < lo1 + 32) m1 &= ~(1u << (p1 - lo1));

    int c = __popc(m0) + __popc(m1);

    // Inclusive warp scan of popcounts.
    int v = c;
    #pragma unroll
    for (int off = 1; off < 32; off <<= 1) {
        int x = __shfl_up_sync(0xffffffffu, v, off);
        if (lane >= off) v += x;
    }
    __shared__ int wsum[16];
    if (lane == 31) wsum[(t >> 5)] = v;
    __syncthreads();
    // Cross-warp scan per half: warp 0 scans half 0's totals, warp 8 half 1's.
    if (hw == 0) {
        int base = half << 3;
        int x = (lane < 8) ? wsum[base + lane] : 0;
        #pragma unroll
        for (int off = 1; off < 8; off <<= 1) {
            int y = __shfl_up_sync(0xffffffffu, x, off);
            if (lane >= off) x += y;
        }
        if (lane < 8) wsum[base + lane] = x;
    }
    __syncthreads();

    int r = v - c + (hw > 0 ? wsum[(half << 3) + hw - 1] : 0);  // exclusive rank

    if (r < TOPK_K) {
        unsigned mm = m0;
        int lo = lo0;
        #pragma unroll
        for (int hwd = 0; hwd < 2; hwd++) {
            while (mm && r < TOPK_K) {
                int bi = __ffs(mm) - 1;
                mm &= mm - 1;
                int bitpos = lo + bi;
                out[E_EDGES + g * TOPK_K + r]       = (float)(boff + (bitpos >> 7));
                out[AUG + E_EDGES + g * TOPK_K + r] = (float)(boff + (bitpos & 127));
                r++;
            }
            mm = m1; lo = lo1;
        }
    }
}

extern "C" void kernel_launch(void* const* d_in, const int* in_sizes, int n_in,
                              void* d_out, int out_size) {
    // Locate edge_index by its unique element count (2 * E = 131072, int32).
    const int* ei = nullptr;
    for (int i = 0; i < n_in; i++) {
        if (in_sizes[i] == 2 * E_EDGES) { ei = (const int*)d_in[i]; break; }
    }
    float* out = (float*)d_out;

    fused_kernel<<<NBLK, 512>>>(ei, out, (out_size > 2 * AUG) ? 1 : 0);
}